// round 4
// baseline (speedup 1.0000x reference)
#include <cuda_runtime.h>

// VectorQuantizer: latents [32,64,64,64] (B,D,H,W), emb [512,64].
// N = 131072 pixels, D=64, K=512.
// out[0..N*D) = straight-through quantized tensor (== q) in (B,D,H,W) layout
// out[out_size-1] = vq_loss = 1.25 * mean((q - lat)^2)
//
// R3: FFMA2 with NO register spills. Pixel kept as 64 scalar floats; the
// packed {x_d,x_d} multiplicand is built with one mov.b64 per (k-tile,d),
// amortized over a 16-code tile (4x LDS.128 + 8x FFMA2). Per-lane rn rounding
// of fma.rn.f32x2 keeps every per-code dot chain bit-identical to reference.

#define VQ_K     512
#define VQ_D     64
#define VQ_HW    4096
#define VQ_NPIX  131072
#define VQ_ND    8388608
#define THREADS  256
#define SMEM_BYTES (VQ_K * VQ_D * 4 + VQ_K * 4)   // 133120 B

__device__ float  g_embT[VQ_D * VQ_K];   // transposed codebook [d][k]
__device__ float  g_sume2[VQ_K];
__device__ double g_loss_acc;

#define FMA2(dst, a, b, c) \
    asm("fma.rn.f32x2 %0, %1, %2, %3;" : "=l"(dst) : "l"(a), "l"(b), "l"(c))
#define PACK2(dst, f) \
    asm("mov.b64 %0, {%1, %1};" : "=l"(dst) : "r"(__float_as_uint(f)))
#define UNPACK2(lo, hi, v) \
    asm("mov.b64 {%0, %1}, %2;" : "=r"(lo), "=r"(hi) : "l"(v))

// ---- setup: 8 blocks, smem-tiled transpose (64 codes per block) + sequential
// ||e||^2 chains + loss-accumulator reset (graph replays must be idempotent).
__global__ void vq_setup_kernel(const float* __restrict__ emb) {
    __shared__ float tile[64][65];                 // 64 codes x 64 dims, padded
    const int kb  = blockIdx.x * 64;
    const int tid = threadIdx.x;

    if (blockIdx.x == 0 && tid == 0) g_loss_acc = 0.0;

    // coalesced load of 64 codes (row-major)
    for (int i = tid; i < 64 * 64; i += THREADS) {
        int k = i >> 6, d = i & 63;
        tile[k][d] = emb[(kb + k) * VQ_D + d];
    }
    __syncthreads();

    // per-code ||e||^2: sequential fp32 mul+add chain (matches reference)
    if (tid < 64) {
        float acc = 0.0f;
#pragma unroll
        for (int d = 0; d < VQ_D; d++) {
            float v = tile[tid][d];
            acc = __fadd_rn(acc, __fmul_rn(v, v));
        }
        g_sume2[kb + tid] = acc;
    }

    // transposed write (consecutive k -> consecutive gmem addresses, coalesced)
    for (int i = tid; i < 64 * 64; i += THREADS) {
        int d = i >> 6, k = i & 63;
        g_embT[d * VQ_K + kb + k] = tile[k][d];
    }
}

// ---- main: one pixel per thread, transposed codebook in smem, FFMA2 dots.
__global__ void __launch_bounds__(THREADS)
vq_main_kernel(const float* __restrict__ lat,
               float* __restrict__ out) {
    extern __shared__ float sm[];               // [D*K] transposed codes, [K] sume2
    float* smT  = sm;
    float* sm_s = sm + VQ_D * VQ_K;

    // stage transposed codebook + sume2 (coalesced float4 copy)
    {
        const float4* src = (const float4*)g_embT;
        float4* dst = (float4*)smT;
        for (int i = threadIdx.x; i < VQ_D * VQ_K / 4; i += THREADS)
            dst[i] = src[i];
        const float4* ssrc = (const float4*)g_sume2;
        float4* sdst = (float4*)sm_s;
        for (int i = threadIdx.x; i < VQ_K / 4; i += THREADS)
            sdst[i] = ssrc[i];
    }
    __syncthreads();

    const int n = blockIdx.x * THREADS + threadIdx.x;    // pixel id
    const int b = n >> 12;
    const int s = n & 4095;
    const long base = (long)b * (VQ_D * VQ_HW) + s;

    // pixel components as 64 scalar floats (coalesced loads), sequential ||x||^2
    float x[VQ_D];
#pragma unroll
    for (int d = 0; d < VQ_D; d++)
        x[d] = lat[base + (long)d * VQ_HW];
    float a = 0.0f;
#pragma unroll
    for (int d = 0; d < VQ_D; d++)
        a = __fadd_rn(a, __fmul_rn(x[d], x[d]));

    float best = 3.4e38f;
    int   bi   = 0;

    // 16 codes per tile: per d, 1 pack + 4x LDS.128 + 8x FFMA2
#pragma unroll 1
    for (int k0 = 0; k0 < VQ_K; k0 += 16) {
        unsigned long long ac0 = 0ull, ac1 = 0ull, ac2 = 0ull, ac3 = 0ull;
        unsigned long long ac4 = 0ull, ac5 = 0ull, ac6 = 0ull, ac7 = 0ull;
#pragma unroll
        for (int d = 0; d < VQ_D; d++) {
            unsigned long long xp;
            PACK2(xp, x[d]);
            const float* row = smT + d * VQ_K + k0;
            ulonglong2 eA = *(const ulonglong2*)(row);
            ulonglong2 eB = *(const ulonglong2*)(row + 4);
            ulonglong2 eC = *(const ulonglong2*)(row + 8);
            ulonglong2 eD = *(const ulonglong2*)(row + 12);
            FMA2(ac0, xp, eA.x, ac0);
            FMA2(ac1, xp, eA.y, ac1);
            FMA2(ac2, xp, eB.x, ac2);
            FMA2(ac3, xp, eB.y, ac3);
            FMA2(ac4, xp, eC.x, ac4);
            FMA2(ac5, xp, eC.y, ac5);
            FMA2(ac6, xp, eD.x, ac6);
            FMA2(ac7, xp, eD.y, ac7);
        }
        // dist = fl( fl(a + s_k) - 2*dot ), ascending-k strict-< tie-break
        unsigned int u[16];
        UNPACK2(u[0],  u[1],  ac0);
        UNPACK2(u[2],  u[3],  ac1);
        UNPACK2(u[4],  u[5],  ac2);
        UNPACK2(u[6],  u[7],  ac3);
        UNPACK2(u[8],  u[9],  ac4);
        UNPACK2(u[10], u[11], ac5);
        UNPACK2(u[12], u[13], ac6);
        UNPACK2(u[14], u[15], ac7);
#pragma unroll
        for (int j = 0; j < 16; j += 4) {
            float4 sv = *(const float4*)(sm_s + k0 + j);
            float dist;
            dist = __fmaf_rn(-2.0f, __uint_as_float(u[j + 0]), __fadd_rn(a, sv.x));
            if (dist < best) { best = dist; bi = k0 + j + 0; }
            dist = __fmaf_rn(-2.0f, __uint_as_float(u[j + 1]), __fadd_rn(a, sv.y));
            if (dist < best) { best = dist; bi = k0 + j + 1; }
            dist = __fmaf_rn(-2.0f, __uint_as_float(u[j + 2]), __fadd_rn(a, sv.z));
            if (dist < best) { best = dist; bi = k0 + j + 2; }
            dist = __fmaf_rn(-2.0f, __uint_as_float(u[j + 3]), __fadd_rn(a, sv.w));
            if (dist < best) { best = dist; bi = k0 + j + 3; }
        }
    }

    // gather winning code, straight-through output, double loss accumulation
    double lacc = 0.0;
#pragma unroll
    for (int d = 0; d < VQ_D; d++) {
        float xd = x[d];
        float qd = smT[d * VQ_K + bi];
        float dm = __fsub_rn(qd, xd);                       // q - lat
        out[base + (long)d * VQ_HW] = __fadd_rn(xd, dm);    // lat + (q - lat)
        lacc += (double)__fmul_rn(dm, dm);
    }

#pragma unroll
    for (int off = 16; off > 0; off >>= 1)
        lacc += __shfl_down_sync(0xFFFFFFFFu, lacc, off);
    if ((threadIdx.x & 31) == 0)
        atomicAdd(&g_loss_acc, lacc);
}

// ---- finalize: vq_loss = fl( fl(m*0.25) + m ), m = mean((q-lat)^2)
__global__ void vq_finalize_kernel(float* __restrict__ out, int out_size) {
    double mean = g_loss_acc / (double)VQ_ND;
    float m = (float)mean;
    out[out_size - 1] = __fadd_rn(__fmul_rn(m, 0.25f), m);
}

extern "C" void kernel_launch(void* const* d_in, const int* in_sizes, int n_in,
                              void* d_out, int out_size) {
    const float* lat = (const float*)d_in[0];
    const float* emb = (const float*)d_in[1];
    float* out = (float*)d_out;

    static bool attr_set = false;
    if (!attr_set) {
        cudaFuncSetAttribute(vq_main_kernel,
                             cudaFuncAttributeMaxDynamicSharedMemorySize,
                             SMEM_BYTES);
        attr_set = true;
    }

    vq_setup_kernel<<<8, THREADS>>>(emb);
    vq_main_kernel<<<VQ_NPIX / THREADS, THREADS, SMEM_BYTES>>>(lat, out);
    vq_finalize_kernel<<<1, 1>>>(out, out_size);
}